// round 4
// baseline (speedup 1.0000x reference)
#include <cuda_runtime.h>
#include <cstdint>
#include <cmath>

// ---------------------------------------------------------------------------
// SpecAugment: out = where(freq_mask[b,f] | time_mask[b,t], 0, x)
// Host computes the 1280 threefry draws (bit-exact, verified rel_err=0.0) and
// passes them as a __grid_constant__ param. Device: ONE kernel, 4 rows per
// block (rows share batch => time mask + nibbles computed once, reused 4x),
// 4 float4/thread/row with loads skipped for masked data.
// ---------------------------------------------------------------------------

#define B_DIM 128
#define F_DIM 80
#define T_DIM 4000
#define T4    1000          // float4 per row
#define TW    125           // 32-bit time-mask words per batch
#define NTHREADS 256
#define ROWS_PER_BLK 4
#define GROUPS_PER_B (F_DIM / ROWS_PER_BLK)   // 20

struct MaskParams {
    uint32_t frow[(B_DIM * F_DIM + 31) / 32];  // bit per (b,f) row
    short ts[B_DIM * 10];                      // time band start
    short te[B_DIM * 10];                      // time band end (exclusive)
};

// ============================ device ======================================

__global__ void __launch_bounds__(NTHREADS)
apply_kernel(const float4* __restrict__ x, float4* __restrict__ out,
             const __grid_constant__ MaskParams p)
{
    const int b    = blockIdx.x / GROUPS_PER_B;
    const int grp  = blockIdx.x % GROUPS_PER_B;
    const int row0 = b * F_DIM + grp * ROWS_PER_BLK;
    const int tid  = threadIdx.x;

    // Build this batch's packed time mask in shared (125 words, 10 bands).
    __shared__ uint32_t s_tb[TW];
    if (tid < TW) {
        const int base = tid * 32;
        uint32_t word = 0u;
#pragma unroll
        for (int m = 0; m < 10; m++) {
            int s = p.ts[b * 10 + m], e = p.te[b * 10 + m];
            int lo = s - base;  lo = lo < 0  ? 0  : lo;
            int hi = e - base;  hi = hi > 32 ? 32 : hi;
            if (hi > lo) {
                uint32_t mhi = (hi >= 32) ? 0xFFFFFFFFu : ((1u << hi) - 1u);
                word |= mhi & ~((1u << lo) - 1u);
            }
        }
        s_tb[tid] = word;
    }
    __syncthreads();

    // Per-t4 nibbles: same for every row in this block (same batch).
    uint32_t nib[4];
#pragma unroll
    for (int i = 0; i < 4; i++) {
        int t4 = tid + i * NTHREADS;
        nib[i] = (t4 < T4) ? ((s_tb[t4 >> 3] >> ((t4 & 7) * 4)) & 0xFu) : 0xFu;
    }

    const float4 z = make_float4(0.f, 0.f, 0.f, 0.f);

#pragma unroll
    for (int r = 0; r < ROWS_PER_BLK; r++) {
        const int row = row0 + r;
        const float4* xr   = x   + (size_t)row * T4;
        float4*       orow = out + (size_t)row * T4;

        if ((p.frow[row >> 5] >> (row & 31)) & 1u) {
            // Entire row frequency-masked: store zeros, read nothing.
#pragma unroll
            for (int i = 0; i < 4; i++) {
                int t4 = tid + i * NTHREADS;
                if (t4 < T4) __stcs(orow + t4, z);
            }
            continue;
        }

        float4 v[4];
        // Front-batched streaming loads; skip fully-masked float4s.
#pragma unroll
        for (int i = 0; i < 4; i++) {
            int t4 = tid + i * NTHREADS;
            v[i] = z;
            if (t4 < T4 && nib[i] != 0xFu) v[i] = __ldcs(xr + t4);
        }
#pragma unroll
        for (int i = 0; i < 4; i++) {
            int t4 = tid + i * NTHREADS;
            if (t4 >= T4) continue;
            float4 o = v[i];
            o.x = (nib[i] & 1u) ? 0.f : o.x;
            o.y = (nib[i] & 2u) ? 0.f : o.y;
            o.z = (nib[i] & 4u) ? 0.f : o.z;
            o.w = (nib[i] & 8u) ? 0.f : o.w;
            __stcs(orow + t4, o);
        }
    }
}

// ============================ host: threefry draws ========================

namespace sa_host {

struct U2 { uint32_t a, b; };

static inline U2 tf(uint32_t k0, uint32_t k1, uint32_t x0, uint32_t x1) {
    const uint32_t ks2 = k0 ^ k1 ^ 0x1BD11BDAu;
    x0 += k0; x1 += k1;
#define RND(r) { x0 += x1; x1 = (x1 << (r)) | (x1 >> (32 - (r))); x1 ^= x0; }
    RND(13) RND(15) RND(26) RND(6)
    x0 += k1;  x1 += ks2 + 1u;
    RND(17) RND(29) RND(16) RND(24)
    x0 += ks2; x1 += k0 + 2u;
    RND(13) RND(15) RND(26) RND(6)
    x0 += k0;  x1 += k1 + 3u;
    RND(17) RND(29) RND(16) RND(24)
    x0 += k1;  x1 += ks2 + 4u;
    RND(13) RND(15) RND(26) RND(6)
    x0 += ks2; x1 += k0 + 5u;
#undef RND
    return U2{x0, x1};
}

// jax_threefry_partitionable = True (verified bit-exact)
static inline U2 split_a(U2 k) { return tf(k.a, k.b, 0u, 0u); }
static inline U2 split_b(U2 k) { return tf(k.a, k.b, 0u, 1u); }
static inline uint32_t rbits(U2 k, uint32_t j) {
    U2 o = tf(k.a, k.b, 0u, j);
    return o.a ^ o.b;
}

static void fill_params(MaskParams& p) {
    U2 key{0u, 42u};                       // jax.random.key(42)
    U2 kf  = split_a(key), kt  = split_b(key);
    U2 kwf = split_a(kf),  ksf = split_b(kf);
    U2 kwt = split_a(kt),  kst = split_b(kt);
    U2 k1f = split_a(kwf), k2f = split_b(kwf);
    U2 k1t = split_a(kwt), k2t = split_b(kwt);

    // Freq: (128, 2) draws, span 28, multiplier 2^32 % 28 = 4
    int fs[B_DIM * 2], fe[B_DIM * 2];
    for (int j = 0; j < B_DIM * 2; j++) {
        uint32_t h  = rbits(k1f, (uint32_t)j);
        uint32_t l  = rbits(k2f, (uint32_t)j);
        uint32_t ub = rbits(ksf, (uint32_t)j);
        uint32_t w  = ((h % 28u) * 4u + (l % 28u)) % 28u;
        float u  = (float)(ub >> 9) * (1.0f / 8388608.0f);  // exact [0,1)
        int hi   = F_DIM - (int)w;                          // max(1,80-w), w<=27
        int s    = (int)(u * (float)hi);
        fs[j] = s; fe[j] = s + (int)w;
    }
    for (int i = 0; i < (int)(sizeof(p.frow) / sizeof(p.frow[0])); i++) p.frow[i] = 0u;
    for (int b = 0; b < B_DIM; b++)
        for (int f = 0; f < F_DIM; f++) {
            bool in = (f >= fs[2 * b]     && f < fe[2 * b]) ||
                      (f >= fs[2 * b + 1] && f < fe[2 * b + 1]);
            if (in) {
                int r = b * F_DIM + f;
                p.frow[r >> 5] |= 1u << (r & 31);
            }
        }

    // Time: (128, 10) draws, span 101, multiplier 2^32 % 101 = 68
    for (int j = 0; j < B_DIM * 10; j++) {
        uint32_t h  = rbits(k1t, (uint32_t)j);
        uint32_t l  = rbits(k2t, (uint32_t)j);
        uint32_t ub = rbits(kst, (uint32_t)j);
        uint32_t w  = ((h % 101u) * 68u + (l % 101u)) % 101u;
        float u  = (float)(ub >> 9) * (1.0f / 8388608.0f);
        int hi   = T_DIM - (int)w;                          // max(1,4000-w), w<=100
        int s    = (int)(u * (float)hi);
        p.ts[j] = (short)s;
        p.te[j] = (short)(s + (int)w);
    }
}

} // namespace sa_host

// ============================ launch ======================================

extern "C" void kernel_launch(void* const* d_in, const int* in_sizes, int n_in,
                              void* d_out, int out_size) {
    (void)in_sizes; (void)n_in; (void)out_size;
    const float4* x   = (const float4*)d_in[0];
    float4*       out = (float4*)d_out;

    MaskParams p;
    sa_host::fill_params(p);

    apply_kernel<<<B_DIM * GROUPS_PER_B, NTHREADS>>>(x, out, p);
}

// round 5
// speedup vs baseline: 1.0450x; 1.0450x over previous
#include <cuda_runtime.h>
#include <cstdint>
#include <cmath>

// ---------------------------------------------------------------------------
// SpecAugment: out = where(freq_mask[b,f] | time_mask[b,t], 0, x)
// Host computes the 1280 threefry draws (bit-exact, verified rel_err=0.0),
// passed as __grid_constant__. Device: 2 rows per block, ALL 8 float4 loads
// front-batched (MLP_p1=8) before any store; time mask + nibbles shared.
// ---------------------------------------------------------------------------

#define B_DIM 128
#define F_DIM 80
#define T_DIM 4000
#define T4    1000          // float4 per row
#define TW    125           // 32-bit time-mask words per batch
#define NTHREADS 256
#define ROWS_PER_BLK 2
#define GROUPS_PER_B (F_DIM / ROWS_PER_BLK)   // 40

struct MaskParams {
    uint32_t frow[(B_DIM * F_DIM + 31) / 32];  // bit per (b,f) row
    short ts[B_DIM * 10];                      // time band start
    short te[B_DIM * 10];                      // time band end (exclusive)
};

// ============================ device ======================================

__global__ void __launch_bounds__(NTHREADS)
apply_kernel(const float4* __restrict__ x, float4* __restrict__ out,
             const __grid_constant__ MaskParams p)
{
    const int b    = blockIdx.x / GROUPS_PER_B;
    const int grp  = blockIdx.x % GROUPS_PER_B;
    const int row0 = b * F_DIM + grp * ROWS_PER_BLK;
    const int row1 = row0 + 1;
    const int tid  = threadIdx.x;

    // Build this batch's packed time mask in shared (125 words, 10 bands).
    __shared__ uint32_t s_tb[TW];
    if (tid < TW) {
        const int base = tid * 32;
        uint32_t word = 0u;
#pragma unroll
        for (int m = 0; m < 10; m++) {
            int s = p.ts[b * 10 + m], e = p.te[b * 10 + m];
            int lo = s - base;  lo = lo < 0  ? 0  : lo;
            int hi = e - base;  hi = hi > 32 ? 32 : hi;
            if (hi > lo) {
                uint32_t mhi = (hi >= 32) ? 0xFFFFFFFFu : ((1u << hi) - 1u);
                word |= mhi & ~((1u << lo) - 1u);
            }
        }
        s_tb[tid] = word;
    }
    __syncthreads();

    // Per-t4 nibbles: same for both rows in this block (same batch).
    uint32_t nib[4];
#pragma unroll
    for (int i = 0; i < 4; i++) {
        int t4 = tid + i * NTHREADS;
        nib[i] = (t4 < T4) ? ((s_tb[t4 >> 3] >> ((t4 & 7) * 4)) & 0xFu) : 0xFu;
    }

    const bool m0 = (p.frow[row0 >> 5] >> (row0 & 31)) & 1u;  // row fully masked
    const bool m1 = (p.frow[row1 >> 5] >> (row1 & 31)) & 1u;

    const float4* xr0 = x + (size_t)row0 * T4;
    const float4* xr1 = x + (size_t)row1 * T4;
    float4* or0 = out + (size_t)row0 * T4;
    float4* or1 = out + (size_t)row1 * T4;

    const float4 z = make_float4(0.f, 0.f, 0.f, 0.f);
    float4 v0[4], v1[4];

    // -------- ALL loads front-batched: up to 8 outstanding per thread -----
#pragma unroll
    for (int i = 0; i < 4; i++) {
        int t4 = tid + i * NTHREADS;
        v0[i] = z;
        if (!m0 && t4 < T4 && nib[i] != 0xFu) v0[i] = __ldcs(xr0 + t4);
    }
#pragma unroll
    for (int i = 0; i < 4; i++) {
        int t4 = tid + i * NTHREADS;
        v1[i] = z;
        if (!m1 && t4 < T4 && nib[i] != 0xFu) v1[i] = __ldcs(xr1 + t4);
    }

    // -------- stores (masked rows already hold zeros; nib maps z -> z) ----
#pragma unroll
    for (int i = 0; i < 4; i++) {
        int t4 = tid + i * NTHREADS;
        if (t4 >= T4) continue;
        float4 o = v0[i];
        o.x = (nib[i] & 1u) ? 0.f : o.x;
        o.y = (nib[i] & 2u) ? 0.f : o.y;
        o.z = (nib[i] & 4u) ? 0.f : o.z;
        o.w = (nib[i] & 8u) ? 0.f : o.w;
        __stcs(or0 + t4, o);
    }
#pragma unroll
    for (int i = 0; i < 4; i++) {
        int t4 = tid + i * NTHREADS;
        if (t4 >= T4) continue;
        float4 o = v1[i];
        o.x = (nib[i] & 1u) ? 0.f : o.x;
        o.y = (nib[i] & 2u) ? 0.f : o.y;
        o.z = (nib[i] & 4u) ? 0.f : o.z;
        o.w = (nib[i] & 8u) ? 0.f : o.w;
        __stcs(or1 + t4, o);
    }
}

// ============================ host: threefry draws ========================

namespace sa_host {

struct U2 { uint32_t a, b; };

static inline U2 tf(uint32_t k0, uint32_t k1, uint32_t x0, uint32_t x1) {
    const uint32_t ks2 = k0 ^ k1 ^ 0x1BD11BDAu;
    x0 += k0; x1 += k1;
#define RND(r) { x0 += x1; x1 = (x1 << (r)) | (x1 >> (32 - (r))); x1 ^= x0; }
    RND(13) RND(15) RND(26) RND(6)
    x0 += k1;  x1 += ks2 + 1u;
    RND(17) RND(29) RND(16) RND(24)
    x0 += ks2; x1 += k0 + 2u;
    RND(13) RND(15) RND(26) RND(6)
    x0 += k0;  x1 += k1 + 3u;
    RND(17) RND(29) RND(16) RND(24)
    x0 += k1;  x1 += ks2 + 4u;
    RND(13) RND(15) RND(26) RND(6)
    x0 += ks2; x1 += k0 + 5u;
#undef RND
    return U2{x0, x1};
}

// jax_threefry_partitionable = True (verified bit-exact)
static inline U2 split_a(U2 k) { return tf(k.a, k.b, 0u, 0u); }
static inline U2 split_b(U2 k) { return tf(k.a, k.b, 0u, 1u); }
static inline uint32_t rbits(U2 k, uint32_t j) {
    U2 o = tf(k.a, k.b, 0u, j);
    return o.a ^ o.b;
}

static void fill_params(MaskParams& p) {
    U2 key{0u, 42u};                       // jax.random.key(42)
    U2 kf  = split_a(key), kt  = split_b(key);
    U2 kwf = split_a(kf),  ksf = split_b(kf);
    U2 kwt = split_a(kt),  kst = split_b(kt);
    U2 k1f = split_a(kwf), k2f = split_b(kwf);
    U2 k1t = split_a(kwt), k2t = split_b(kwt);

    // Freq: (128, 2) draws, span 28, multiplier 2^32 % 28 = 4
    int fs[B_DIM * 2], fe[B_DIM * 2];
    for (int j = 0; j < B_DIM * 2; j++) {
        uint32_t h  = rbits(k1f, (uint32_t)j);
        uint32_t l  = rbits(k2f, (uint32_t)j);
        uint32_t ub = rbits(ksf, (uint32_t)j);
        uint32_t w  = ((h % 28u) * 4u + (l % 28u)) % 28u;
        float u  = (float)(ub >> 9) * (1.0f / 8388608.0f);  // exact [0,1)
        int hi   = F_DIM - (int)w;                          // max(1,80-w), w<=27
        int s    = (int)(u * (float)hi);
        fs[j] = s; fe[j] = s + (int)w;
    }
    for (int i = 0; i < (int)(sizeof(p.frow) / sizeof(p.frow[0])); i++) p.frow[i] = 0u;
    for (int b = 0; b < B_DIM; b++)
        for (int f = 0; f < F_DIM; f++) {
            bool in = (f >= fs[2 * b]     && f < fe[2 * b]) ||
                      (f >= fs[2 * b + 1] && f < fe[2 * b + 1]);
            if (in) {
                int r = b * F_DIM + f;
                p.frow[r >> 5] |= 1u << (r & 31);
            }
        }

    // Time: (128, 10) draws, span 101, multiplier 2^32 % 101 = 68
    for (int j = 0; j < B_DIM * 10; j++) {
        uint32_t h  = rbits(k1t, (uint32_t)j);
        uint32_t l  = rbits(k2t, (uint32_t)j);
        uint32_t ub = rbits(kst, (uint32_t)j);
        uint32_t w  = ((h % 101u) * 68u + (l % 101u)) % 101u;
        float u  = (float)(ub >> 9) * (1.0f / 8388608.0f);
        int hi   = T_DIM - (int)w;                          // max(1,4000-w), w<=100
        int s    = (int)(u * (float)hi);
        p.ts[j] = (short)s;
        p.te[j] = (short)(s + (int)w);
    }
}

} // namespace sa_host

// ============================ launch ======================================

extern "C" void kernel_launch(void* const* d_in, const int* in_sizes, int n_in,
                              void* d_out, int out_size) {
    (void)in_sizes; (void)n_in; (void)out_size;
    const float4* x   = (const float4*)d_in[0];
    float4*       out = (float4*)d_out;

    MaskParams p;
    sa_host::fill_params(p);

    apply_kernel<<<B_DIM * GROUPS_PER_B, NTHREADS>>>(x, out, p);
}